// round 13
// baseline (speedup 1.0000x reference)
#include <cuda_runtime.h>
#include <math.h>

#define BATCH 32
#define NROI 1000
#define NCLS 81
#define MAXI 100
#define BPI 32                  // kernel A blocks per image
#define RPB 32                  // ROIs per A-block
#define BT 256
#define BCAP 128                // per-(img,cls) bucket capacity
#define KCAP 1024               // kept-list capacity (>= max M)

// per-(img,cls) buckets (zero-init; g_bcnt/g_done reset by epilogue each run)
__device__ float2 g_bmeta[BATCH * NCLS * BCAP];   // {score, origidx}
__device__ float4 g_bbox4[BATCH * NCLS * BCAP];
__device__ unsigned char g_bkeep[BATCH * NCLS * BCAP];
__device__ int    g_bcnt[BATCH * NCLS];
__device__ int    g_done[BATCH];

// ---------------------------------------------------------------------------
// Kernel A: tile load -> smem argmax -> box regression -> per-class bucket
// ---------------------------------------------------------------------------
__global__ __launch_bounds__(BT, 8)
void detA_kernel(const float* __restrict__ rois,
                 const float* __restrict__ probs,
                 const float* __restrict__ bbox,
                 const float* __restrict__ std_dev)
{
    __shared__ float sp[RPB * NCLS + 4];

    const int img = blockIdx.x / BPI;
    const int sub = blockIdx.x - img * BPI;
    const int t   = threadIdx.x;

    const int row0  = sub * RPB;
    const int nrows = min(RPB, NROI - row0);

    const size_t s0 = ((size_t)img * NROI + row0) * NCLS;
    const int sh  = (int)(s0 & 3);
    const int NEL = nrows * NCLS;
    const int h   = (4 - sh) & 3;

    if (t < h) sp[sh + t] = probs[s0 + t];
    const int nvec = (NEL - h) >> 2;
    const float4* gp = (const float4*)(probs + s0 + h);
    float4* spv = (float4*)(sp + sh + h);
    for (int i = t; i < nvec; i += BT) spv[i] = gp[i];
    const int tl = NEL - h - 4 * nvec;
    if (t < tl) { int e = h + 4 * nvec + t; sp[sh + e] = probs[s0 + e]; }
    __syncthreads();

    if (t < nrows) {
        const float* row = sp + sh + t * NCLS;
        float b0 = row[0]; int i0 = 0;
        float b1 = row[1]; int i1 = 1;
        float b2 = row[2]; int i2 = 2;
        #pragma unroll 13
        for (int c = 3; c < 81; c += 3) {
            float v0 = row[c];
            float v1 = row[c + 1];
            float v2 = row[c + 2];
            if (v0 > b0) { b0 = v0; i0 = c; }
            if (v1 > b1) { b1 = v1; i1 = c + 1; }
            if (v2 > b2) { b2 = v2; i2 = c + 2; }
        }
        float best = b0; int bi = i0;
        if (b1 > best || (b1 == best && i1 < bi)) { best = b1; bi = i1; }
        if (b2 > best || (b2 == best && i2 < bi)) { best = b2; bi = i2; }

        if (bi > 0 && best >= 0.7f) {
            const int r = row0 + t;
            const size_t gri = (size_t)img * NROI + r;
            const float4 sd = *(const float4*)std_dev;
            const float4 dv = *(const float4*)(bbox + (gri * NCLS + bi) * 4);
            const float4 ro = *(const float4*)(rois + gri * 4);

            float d0 = dv.x * sd.x, d1 = dv.y * sd.y, d2 = dv.z * sd.z, d3 = dv.w * sd.w;
            float hh = ro.z - ro.x;
            float ww = ro.w - ro.y;
            float cy = ro.x + 0.5f * hh + d0 * hh;
            float cx = ro.y + 0.5f * ww + d1 * ww;
            hh *= expf(d2);
            ww *= expf(d3);
            float ny1 = cy - 0.5f * hh;
            float nx1 = cx - 0.5f * ww;
            float ny2 = ny1 + hh;
            float nx2 = nx1 + ww;
            ny1 = fminf(fmaxf(ny1, 0.0f), 1.0f);
            nx1 = fminf(fmaxf(nx1, 0.0f), 1.0f);
            ny2 = fminf(fmaxf(ny2, 0.0f), 1.0f);
            nx2 = fminf(fmaxf(nx2, 0.0f), 1.0f);

            const int bk = img * NCLS + bi;
            int pos = atomicAdd(&g_bcnt[bk], 1);
            if (pos < BCAP) {
                g_bmeta[bk * BCAP + pos] = make_float2(best, (float)r);
                g_bbox4[bk * BCAP + pos] = make_float4(ny1, nx1, ny2, nx2);
            }
        }
    }
}

// ---------------------------------------------------------------------------
// Kernel B: one block per (img, cls): sort + greedy NMS on a tiny bucket.
// Last block per image (ticket) gathers kept entries and emits output.
// ---------------------------------------------------------------------------
__global__ __launch_bounds__(BT)
void detB_kernel(float* __restrict__ out)
{
    // class-phase fallback (33..128 members)
    __shared__ float f_score[BCAP];
    __shared__ short f_idx[BCAP];
    __shared__ float f_box[BCAP * 4];
    __shared__ short f_orig[BCAP];          // sorted rank -> original bucket slot
    __shared__ unsigned char f_keep[BCAP];
    // epilogue
    __shared__ float k_score[KCAP];
    __shared__ short k_idx[KCAP];
    __shared__ short k_cls[KCAP];
    __shared__ float4 k_box[KCAP];
    __shared__ int   s_bcnt[NCLS];
    __shared__ int   s_K;
    __shared__ float s_out[MAXI * 6];
    __shared__ int   s_last;

    const int img = blockIdx.x / NCLS;
    const int cls = blockIdx.x - img * NCLS;
    const int t   = threadIdx.x;
    const int wid = t >> 5;
    const int lane = t & 31;

    const int bk   = img * NCLS + cls;
    const int base = bk * BCAP;
    const int n    = min(g_bcnt[bk], BCAP);

    // ---------------- class phase: sort + greedy NMS within bucket ----------------
    if (n > 32) {
        // smem fallback path (rare)
        if (t < n) {
            float2 m = g_bmeta[base + t];
            float4 b4 = g_bbox4[base + t];
            f_score[t] = m.x;
            f_idx[t]   = (short)m.y;
            f_box[t * 4 + 0] = b4.x;
            f_box[t * 4 + 1] = b4.y;
            f_box[t * 4 + 2] = b4.z;
            f_box[t * 4 + 3] = b4.w;
        }
        __syncthreads();
        // rank sort into f_orig (score desc, idx asc)
        if (t < n) {
            float sc = f_score[t]; short id = f_idx[t];
            int rank = 0;
            for (int j = 0; j < n; ++j) {
                float sj = f_score[j];
                rank += (sj > sc) || (sj == sc && f_idx[j] < id);
            }
            f_orig[rank] = (short)t;
            f_keep[rank] = 1;
        }
        __syncthreads();
        if (wid == 0) {
            for (int a = 0; a < n - 1; ++a) {
                if (!f_keep[a]) continue;
                int oa = f_orig[a];
                float ay1 = f_box[oa * 4 + 0];
                float ax1 = f_box[oa * 4 + 1];
                float ay2 = f_box[oa * 4 + 2];
                float ax2 = f_box[oa * 4 + 3];
                float aa = (ay2 - ay1) * (ax2 - ax1);
                for (int q = a + 1 + lane; q < n; q += 32) {
                    if (!f_keep[q]) continue;
                    int oq = f_orig[q];
                    float by1 = f_box[oq * 4 + 0];
                    float bx1 = f_box[oq * 4 + 1];
                    float by2 = f_box[oq * 4 + 2];
                    float bx2 = f_box[oq * 4 + 3];
                    float ab = (by2 - by1) * (bx2 - bx1);
                    float ih = fmaxf(fminf(ay2, by2) - fmaxf(ay1, by1), 0.0f);
                    float iw = fmaxf(fminf(ax2, bx2) - fmaxf(ax1, bx1), 0.0f);
                    float inter = ih * iw;
                    float iou = inter / fmaxf(aa + ab - inter, 1e-8f);
                    if (iou > 0.3f) f_keep[q] = 0;
                }
                __syncwarp();
            }
        }
        __syncthreads();
        if (t < n) g_bkeep[base + f_orig[t]] = f_keep[t];
    } else if (n > 0) {
        // register-resident warp path (common)
        if (wid == 0) {
            const bool v = (lane < n);
            float sc = -1.0f, idf = 1e9f;
            float by1 = 0, bx1 = 0, by2 = 0, bx2 = 0;
            if (v) {
                float2 m = g_bmeta[base + lane];
                float4 b4 = g_bbox4[base + lane];
                sc = m.x; idf = m.y;
                by1 = b4.x; bx1 = b4.y; by2 = b4.z; bx2 = b4.w;
            }
            // rank among valid (score desc, idx asc)
            int rank = v ? 0 : 999;
            for (int m2 = 0; m2 < n; ++m2) {
                float s2 = __shfl_sync(0xffffffffu, sc,  m2);
                float i2 = __shfl_sync(0xffffffffu, idf, m2);
                if (v) rank += (s2 > sc) || (s2 == sc && i2 < idf);
            }
            int keep = v ? 1 : 0;
            float area = (by2 - by1) * (bx2 - bx1);
            for (int a = 0; a < n - 1; ++a) {
                unsigned am = __ballot_sync(0xffffffffu, rank == a);
                int src = __ffs(am) - 1;
                int ks  = __shfl_sync(0xffffffffu, keep, src);
                float sy1 = __shfl_sync(0xffffffffu, by1, src);
                float sx1 = __shfl_sync(0xffffffffu, bx1, src);
                float sy2 = __shfl_sync(0xffffffffu, by2, src);
                float sx2 = __shfl_sync(0xffffffffu, bx2, src);
                float sa  = __shfl_sync(0xffffffffu, area, src);
                if (ks && keep && rank > a) {
                    float ih = fmaxf(fminf(sy2, by2) - fmaxf(sy1, by1), 0.0f);
                    float iw = fmaxf(fminf(sx2, bx2) - fmaxf(sx1, bx1), 0.0f);
                    float inter = ih * iw;
                    float iou = inter / fmaxf(sa + area - inter, 1e-8f);
                    if (iou > 0.3f) keep = 0;
                }
            }
            if (v) g_bkeep[base + lane] = (unsigned char)keep;
        }
    }

    // ---------------- ticket: last class-block of this image does output ----------
    __syncthreads();
    if (t == 0) {
        __threadfence();
        int tick = atomicAdd(&g_done[img], 1);
        s_last = (tick == NCLS - 1) ? 1 : 0;
    }
    __syncthreads();
    if (!s_last) return;
    __threadfence();   // acquire: all class-blocks' keep flags visible

    // ---------------- epilogue: gather kept, rank = output slot, emit -------------
    if (t < NCLS) s_bcnt[t] = min(g_bcnt[img * NCLS + t], BCAP);
    if (t == 0) s_K = 0;
    for (int o = t; o < MAXI * 6; o += BT) s_out[o] = 0.0f;
    __syncthreads();

    for (int s = t; s < NCLS * BCAP; s += BT) {
        const int c = s >> 7;            // / BCAP (128)
        const int i = s & (BCAP - 1);
        if (i < s_bcnt[c]) {
            const int off = (img * NCLS + c) * BCAP + i;
            if (g_bkeep[off]) {
                float2 m = g_bmeta[off];
                float4 b4 = g_bbox4[off];
                int p = atomicAdd(&s_K, 1);
                if (p < KCAP) {
                    k_score[p] = m.x;
                    k_idx[p]   = (short)m.y;
                    k_cls[p]   = (short)c;
                    k_box[p]   = b4;
                }
            }
        }
    }
    __syncthreads();
    const int K = min(s_K, KCAP);

    // rank among kept (score desc, idx asc) == output slot
    for (int e = t; e < K; e += BT) {
        const float sc = k_score[e];
        const short id = k_idx[e];
        int rank = 0;
        for (int j = 0; j < K; ++j) {
            float sj = k_score[j];
            rank += (sj > sc) || (sj == sc && k_idx[j] < id);
        }
        if (rank < MAXI) {
            float4 b4 = k_box[e];
            s_out[rank * 6 + 0] = b4.x;
            s_out[rank * 6 + 1] = b4.y;
            s_out[rank * 6 + 2] = b4.z;
            s_out[rank * 6 + 3] = b4.w;
            s_out[rank * 6 + 4] = (float)k_cls[e];
            s_out[rank * 6 + 5] = sc;
        }
    }
    __syncthreads();

    float* ob = out + (size_t)img * MAXI * 6;
    for (int o = t; o < MAXI * 6; o += BT) ob[o] = s_out[o];

    // reset counters for next graph replay
    if (t < NCLS) g_bcnt[img * NCLS + t] = 0;
    if (t == 0) g_done[img] = 0;
}

extern "C" void kernel_launch(void* const* d_in, const int* in_sizes, int n_in,
                              void* d_out, int out_size)
{
    const float* rois    = (const float*)d_in[0];
    const float* probs   = (const float*)d_in[1];
    const float* bbox    = (const float*)d_in[2];
    const float* std_dev = (const float*)d_in[3];
    float* out = (float*)d_out;

    detA_kernel<<<BATCH * BPI, BT>>>(rois, probs, bbox, std_dev);
    detB_kernel<<<BATCH * NCLS, BT>>>(out);
}

// round 14
// speedup vs baseline: 2.6917x; 2.6917x over previous
#include <cuda_runtime.h>
#include <math.h>

#define BATCH 32
#define NROI 1000
#define NCLS 81
#define MAXI 100
#define NTOT (BATCH * NROI)
#define BPI 32
#define RPB 32
#define BT 256
#define BT2 1024
#define FULL 0xffffffffu

// compacted per-image lists (zero-init; g_cnt reset by kernel B each run)
__device__ float4 g_cbox[NTOT];
__device__ float4 g_cmeta[NTOT];   // {score, cls, origidx, 0}
__device__ int    g_cnt[BATCH];

// ---------------------------------------------------------------------------
// Kernel A: proven phase 1 (tile load -> smem argmax -> compact valid)
// ---------------------------------------------------------------------------
__global__ __launch_bounds__(BT, 8)
void detA_kernel(const float* __restrict__ rois,
                 const float* __restrict__ probs,
                 const float* __restrict__ bbox,
                 const float* __restrict__ std_dev)
{
    __shared__ float sp[RPB * NCLS + 4];

    const int img = blockIdx.x / BPI;
    const int sub = blockIdx.x - img * BPI;
    const int t   = threadIdx.x;

    const int row0  = sub * RPB;
    const int nrows = min(RPB, NROI - row0);

    const size_t s0 = ((size_t)img * NROI + row0) * NCLS;
    const int sh  = (int)(s0 & 3);
    const int NEL = nrows * NCLS;
    const int h   = (4 - sh) & 3;

    if (t < h) sp[sh + t] = probs[s0 + t];
    const int nvec = (NEL - h) >> 2;
    const float4* gp = (const float4*)(probs + s0 + h);
    float4* spv = (float4*)(sp + sh + h);
    for (int i = t; i < nvec; i += BT) spv[i] = gp[i];
    const int tl = NEL - h - 4 * nvec;
    if (t < tl) { int e = h + 4 * nvec + t; sp[sh + e] = probs[s0 + e]; }
    __syncthreads();

    if (t < nrows) {
        const float* row = sp + sh + t * NCLS;
        float b0 = row[0]; int i0 = 0;
        float b1 = row[1]; int i1 = 1;
        float b2 = row[2]; int i2 = 2;
        #pragma unroll 13
        for (int c = 3; c < 81; c += 3) {
            float v0 = row[c];
            float v1 = row[c + 1];
            float v2 = row[c + 2];
            if (v0 > b0) { b0 = v0; i0 = c; }
            if (v1 > b1) { b1 = v1; i1 = c + 1; }
            if (v2 > b2) { b2 = v2; i2 = c + 2; }
        }
        float best = b0; int bi = i0;
        if (b1 > best || (b1 == best && i1 < bi)) { best = b1; bi = i1; }
        if (b2 > best || (b2 == best && i2 < bi)) { best = b2; bi = i2; }

        if (bi > 0 && best >= 0.7f) {
            const int r = row0 + t;
            const size_t gri = (size_t)img * NROI + r;
            const float4 sd = *(const float4*)std_dev;
            const float4 dv = *(const float4*)(bbox + (gri * NCLS + bi) * 4);
            const float4 ro = *(const float4*)(rois + gri * 4);

            float d0 = dv.x * sd.x, d1 = dv.y * sd.y, d2 = dv.z * sd.z, d3 = dv.w * sd.w;
            float hh = ro.z - ro.x;
            float ww = ro.w - ro.y;
            float cy = ro.x + 0.5f * hh + d0 * hh;
            float cx = ro.y + 0.5f * ww + d1 * ww;
            hh *= expf(d2);
            ww *= expf(d3);
            float ny1 = cy - 0.5f * hh;
            float nx1 = cx - 0.5f * ww;
            float ny2 = ny1 + hh;
            float nx2 = nx1 + ww;
            ny1 = fminf(fmaxf(ny1, 0.0f), 1.0f);
            nx1 = fminf(fmaxf(nx1, 0.0f), 1.0f);
            ny2 = fminf(fmaxf(ny2, 0.0f), 1.0f);
            nx2 = fminf(fmaxf(nx2, 0.0f), 1.0f);

            int pos = atomicAdd(&g_cnt[img], 1);
            if (pos < NROI) {
                g_cbox[img * NROI + pos]  = make_float4(ny1, nx1, ny2, nx2);
                g_cmeta[img * NROI + pos] = make_float4(best, (float)bi, (float)r, 0.0f);
            }
        }
    }
}

// ---------------------------------------------------------------------------
// Kernel B: minimal-chain per-image epilogue (grid 32, 1024 threads)
// ---------------------------------------------------------------------------
__global__ __launch_bounds__(BT2)
void detB_kernel(float* __restrict__ out)
{
    __shared__ float  s_score[NROI];     // 4 KB (entry id indexed)
    __shared__ short  s_idx[NROI];       // 2 KB
    __shared__ short  s_cls[NROI];       // 2 KB
    __shared__ float4 s_box[NROI];       // 16 KB
    __shared__ short  s_perm[NROI];      // 2 KB  class-grouped (unsorted)
    __shared__ short  s_sort[NROI];      // 2 KB  class-grouped sorted entry ids
    __shared__ unsigned char s_kp[NROI]; // 1 KB  keep, by sorted position
    __shared__ int    s_ccount[NCLS];
    __shared__ int    s_cstart[NCLS];
    __shared__ int    s_ccur[NCLS];
    __shared__ float  k_score[NROI];     // 4 KB  kept compacted
    __shared__ short  k_idx[NROI];       // 2 KB
    __shared__ short  k_ent[NROI];       // 2 KB
    __shared__ float  s_out[MAXI * 6];   // 2.4 KB
    __shared__ int    s_wsum[32];
    __shared__ int    s_K;

    const int b = blockIdx.x;
    const int t = threadIdx.x;
    const int wid = t >> 5;
    const int lane = t & 31;
    const int base = b * NROI;
    const int M = min(g_cnt[b], NROI);

    if (t < NCLS) { s_ccount[t] = 0; s_ccur[t] = 0; }
    for (int o = t; o < MAXI * 6; o += BT2) s_out[o] = 0.0f;

    // ---- phase 1: load entries, count classes ----
    int mycls = -1;
    if (t < M) {
        float4 m  = g_cmeta[base + t];     // independent loads, both in flight
        float4 bx = g_cbox[base + t];
        s_score[t] = m.x;
        s_cls[t]   = (short)m.y;
        s_idx[t]   = (short)m.z;
        s_box[t]   = bx;
        mycls = (int)m.y;
    }
    __syncthreads();
    if (mycls >= 0) atomicAdd(&s_ccount[mycls], 1);
    __syncthreads();

    // ---- phase 2: warp0 shfl-scan of 81 class counts -> s_cstart ----
    if (wid == 0) {
        const int c0 = lane, c1 = lane + 32, c2 = lane + 64;
        int v0 = s_ccount[c0];
        int v1 = (c1 < NCLS) ? s_ccount[c1] : 0;
        int v2 = (c2 < NCLS) ? s_ccount[c2] : 0;
        int i0 = v0, i1 = v1, i2 = v2;
        #pragma unroll
        for (int off = 1; off < 32; off <<= 1) {
            int n0 = __shfl_up_sync(FULL, i0, off);
            int n1 = __shfl_up_sync(FULL, i1, off);
            int n2 = __shfl_up_sync(FULL, i2, off);
            if (lane >= off) { i0 += n0; i1 += n1; i2 += n2; }
        }
        const int tot0 = __shfl_sync(FULL, i0, 31);
        const int tot1 = __shfl_sync(FULL, i1, 31);
        s_cstart[c0] = i0 - v0;
        if (c1 < NCLS) s_cstart[c1] = tot0 + i1 - v1;
        if (c2 < NCLS) s_cstart[c2] = tot0 + tot1 + i2 - v2;
    }
    __syncthreads();

    // ---- phase 3: scatter entries into class regions (unstable) ----
    if (mycls >= 0) {
        int p = s_cstart[mycls] + atomicAdd(&s_ccur[mycls], 1);
        s_perm[p] = (short)t;
    }
    __syncthreads();

    // ---- phase 4: warp-per-class sort + greedy NMS ----
    for (int c = wid; c < NCLS; c += 32) {
        const int cs = s_cstart[c];
        const int n  = s_ccount[c];
        if (n <= 0) continue;
        if (n <= 32) {
            // register path
            const bool v = (lane < n);
            int e = 0; float sc = -1.0f, idf = 1e9f;
            float4 bb = make_float4(0.f, 0.f, 0.f, 0.f);
            if (v) {
                e = s_perm[cs + lane];
                sc = s_score[e]; idf = (float)s_idx[e];
                bb = s_box[e];
            }
            int rank = v ? 0 : 999;
            for (int m2 = 0; m2 < n; ++m2) {
                float s2 = __shfl_sync(FULL, sc,  m2);
                float i2 = __shfl_sync(FULL, idf, m2);
                if (v) rank += (s2 > sc) || (s2 == sc && i2 < idf);
            }
            int keep = v ? 1 : 0;
            float area = (bb.z - bb.x) * (bb.w - bb.y);
            for (int a = 0; a < n - 1; ++a) {
                unsigned am = __ballot_sync(FULL, rank == a);
                int src = __ffs(am) - 1;
                int ks  = __shfl_sync(FULL, keep, src);
                float sy1 = __shfl_sync(FULL, bb.x, src);
                float sx1 = __shfl_sync(FULL, bb.y, src);
                float sy2 = __shfl_sync(FULL, bb.z, src);
                float sx2 = __shfl_sync(FULL, bb.w, src);
                float sa  = __shfl_sync(FULL, area, src);
                if (ks && keep && rank > a) {
                    float ih = fmaxf(fminf(sy2, bb.z) - fmaxf(sy1, bb.x), 0.0f);
                    float iw = fmaxf(fminf(sx2, bb.w) - fmaxf(sx1, bb.y), 0.0f);
                    float inter = ih * iw;
                    float iou = inter / fmaxf(sa + area - inter, 1e-8f);
                    if (iou > 0.3f) keep = 0;
                }
            }
            if (v) { s_sort[cs + rank] = (short)e; s_kp[cs + rank] = (unsigned char)keep; }
        } else {
            // smem path (rare big class)
            for (int p = lane; p < n; p += 32) {
                int e = s_perm[cs + p];
                float sc = s_score[e]; short id = s_idx[e];
                int rank = 0;
                for (int j = 0; j < n; ++j) {
                    int ej = s_perm[cs + j];
                    float sj = s_score[ej];
                    rank += (sj > sc) || (sj == sc && s_idx[ej] < id);
                }
                s_sort[cs + rank] = (short)e;
                s_kp[cs + rank] = 1;
            }
            __syncwarp();
            for (int a = 0; a < n - 1; ++a) {
                if (!s_kp[cs + a]) continue;        // warp-uniform
                int ea = s_sort[cs + a];
                float4 ba = s_box[ea];
                float aa = (ba.z - ba.x) * (ba.w - ba.y);
                for (int q = a + 1 + lane; q < n; q += 32) {
                    if (!s_kp[cs + q]) continue;
                    int eq = s_sort[cs + q];
                    float4 bq = s_box[eq];
                    float ab = (bq.z - bq.x) * (bq.w - bq.y);
                    float ih = fmaxf(fminf(ba.z, bq.z) - fmaxf(ba.x, bq.x), 0.0f);
                    float iw = fmaxf(fminf(ba.w, bq.w) - fmaxf(ba.y, bq.y), 0.0f);
                    float inter = ih * iw;
                    float iou = inter / fmaxf(aa + ab - inter, 1e-8f);
                    if (iou > 0.3f) s_kp[cs + q] = 0;
                }
                __syncwarp();
            }
        }
    }
    __syncthreads();

    // ---- phase 5: compact kept entries (single ballot scan; M < 1024) ----
    int kflag = 0; int e = -1;
    if (t < M && s_kp[t]) { kflag = 1; e = s_sort[t]; }
    {
        unsigned mask = __ballot_sync(FULL, kflag);
        if (lane == 0) s_wsum[wid] = __popc(mask);
        __syncthreads();
        if (wid == 0) {
            int v = s_wsum[lane];
            int inc = v;
            #pragma unroll
            for (int off = 1; off < 32; off <<= 1) {
                int nn = __shfl_up_sync(FULL, inc, off);
                if (lane >= off) inc += nn;
            }
            s_wsum[lane] = inc - v;                    // exclusive
            if (lane == 31) s_K = inc;
        }
        __syncthreads();
        int slot = s_wsum[wid] + __popc(mask & ((1u << lane) - 1));
        if (kflag) {
            k_score[slot] = s_score[e];
            k_idx[slot]   = s_idx[e];
            k_ent[slot]   = (short)e;
        }
    }
    __syncthreads();
    const int K = s_K;

    // ---- phase 6: rank kept globally (score desc, idx asc) == output slot ----
    if (t < K) {
        float sc = k_score[t]; short id = k_idx[t];
        int rank = 0;
        for (int j = 0; j < K; ++j) {
            float sj = k_score[j];                     // broadcast LDS
            rank += (sj > sc) || (sj == sc && k_idx[j] < id);
        }
        if (rank < MAXI) {
            int ee = k_ent[t];
            float4 b4 = s_box[ee];
            s_out[rank * 6 + 0] = b4.x;
            s_out[rank * 6 + 1] = b4.y;
            s_out[rank * 6 + 2] = b4.z;
            s_out[rank * 6 + 3] = b4.w;
            s_out[rank * 6 + 4] = (float)s_cls[ee];
            s_out[rank * 6 + 5] = sc;
        }
    }
    __syncthreads();

    float* ob = out + (size_t)b * MAXI * 6;
    for (int o = t; o < MAXI * 6; o += BT2) ob[o] = s_out[o];

    if (t == 0) g_cnt[b] = 0;   // reset for next graph replay
}

extern "C" void kernel_launch(void* const* d_in, const int* in_sizes, int n_in,
                              void* d_out, int out_size)
{
    const float* rois    = (const float*)d_in[0];
    const float* probs   = (const float*)d_in[1];
    const float* bbox    = (const float*)d_in[2];
    const float* std_dev = (const float*)d_in[3];
    float* out = (float*)d_out;

    detA_kernel<<<BATCH * BPI, BT>>>(rois, probs, bbox, std_dev);
    detB_kernel<<<BATCH, BT2>>>(out);
}